// round 1
// baseline (speedup 1.0000x reference)
#include <cuda_runtime.h>
#include <cuda_bf16.h>

#define BB 64
#define NN 512
#define CC 1024

// Scratch (allocation-free rule: __device__ globals)
__device__ float g_S[(size_t)BB * NN * NN];      // 67 MB gram matrices
__device__ float g_thr[BB * NN];                 // per-row 32nd-largest value
__device__ float g_rdeg[BB * NN];                // per-row 1/sqrt(degree)

// ---------------------------------------------------------------------------
// Kernel A: S[b] = X[b] * X[b]^T, exploiting symmetry (only jt >= it tiles).
// 128x128 tile per CTA, 256 threads, 8x8 micro-tile per thread (split 4+4).
// ---------------------------------------------------------------------------
__global__ __launch_bounds__(256, 2)
void gemm_xxt_kernel(const float* __restrict__ X)
{
    // 10 tile pairs for 4x4 tile grid, jt >= it
    const unsigned char ITm[10] = {0,0,0,0,1,1,1,2,2,3};
    const unsigned char JTm[10] = {0,1,2,3,1,2,3,2,3,3};
    const int it = ITm[blockIdx.x];
    const int jt = JTm[blockIdx.x];
    const int b  = blockIdx.y;

    const float* __restrict__ Xb = X + (size_t)b * NN * CC;

    __shared__ float As[16][128];
    __shared__ float Bs[16][128];

    const int tid = threadIdx.x;
    const int tx = tid & 15;        // 0..15 -> columns
    const int ty = tid >> 4;        // 0..15 -> rows

    float acc[8][8];
    #pragma unroll
    for (int a = 0; a < 8; a++)
        #pragma unroll
        for (int c = 0; c < 8; c++)
            acc[a][c] = 0.0f;

    const int rbase = it * 128;
    const int cbase = jt * 128;

    for (int k0 = 0; k0 < CC; k0 += 16) {
        // Load 128x16 A tile and 128x16 B tile (both are rows of X).
        #pragma unroll
        for (int p = 0; p < 2; p++) {
            int l   = tid + p * 256;      // 0..511
            int row = l >> 2;             // 0..127
            int k4  = (l & 3) * 4;        // 0,4,8,12
            float4 va = *(const float4*)(Xb + (size_t)(rbase + row) * CC + k0 + k4);
            As[k4 + 0][row] = va.x;
            As[k4 + 1][row] = va.y;
            As[k4 + 2][row] = va.z;
            As[k4 + 3][row] = va.w;
            float4 vb = *(const float4*)(Xb + (size_t)(cbase + row) * CC + k0 + k4);
            Bs[k4 + 0][row] = vb.x;
            Bs[k4 + 1][row] = vb.y;
            Bs[k4 + 2][row] = vb.z;
            Bs[k4 + 3][row] = vb.w;
        }
        __syncthreads();

        #pragma unroll
        for (int k = 0; k < 16; k++) {
            float4 a0 = *(const float4*)&As[k][ty * 4];
            float4 a1 = *(const float4*)&As[k][ty * 4 + 64];
            float4 b0 = *(const float4*)&Bs[k][tx * 4];
            float4 b1 = *(const float4*)&Bs[k][tx * 4 + 64];
            float ar[8] = {a0.x, a0.y, a0.z, a0.w, a1.x, a1.y, a1.z, a1.w};
            float br[8] = {b0.x, b0.y, b0.z, b0.w, b1.x, b1.y, b1.z, b1.w};
            #pragma unroll
            for (int a = 0; a < 8; a++)
                #pragma unroll
                for (int c = 0; c < 8; c++)
                    acc[a][c] = fmaf(ar[a], br[c], acc[a][c]);
        }
        __syncthreads();
    }

    float* __restrict__ Sb = g_S + (size_t)b * NN * NN;
    #pragma unroll
    for (int a = 0; a < 8; a++) {
        int gr = rbase + ((a < 4) ? (ty * 4 + a) : (64 + ty * 4 + a - 4));
        #pragma unroll
        for (int c = 0; c < 8; c++) {
            int gc = cbase + ((c < 4) ? (tx * 4 + c) : (64 + tx * 4 + c - 4));
            Sb[(size_t)gr * NN + gc] = acc[a][c];
            if (jt > it)
                Sb[(size_t)gc * NN + gr] = acc[a][c];   // mirror
        }
    }
}

// ---------------------------------------------------------------------------
// Kernel B: per row, exact 32nd-largest value (ties handled like jax top_k)
// then degree = count(S >= thr). One CTA (256 thr) per row; each thread owns
// 2 elements in registers; 32 rounds of block-max + claim-one removal.
// ---------------------------------------------------------------------------
__global__ __launch_bounds__(256)
void topk_threshold_kernel()
{
    const int row = blockIdx.x;                 // 0 .. BB*NN-1
    const float* __restrict__ Sr = g_S + (size_t)row * NN;
    const int tid = threadIdx.x;

    const float o0 = Sr[tid];
    const float o1 = Sr[tid + 256];
    float v0 = o0, v1 = o1;

    __shared__ float wred[8];
    __shared__ float sbest;
    __shared__ int   claim;

    const float NEG_INF = __int_as_float(0xff800000);
    float thr = NEG_INF;

    for (int iter = 0; iter < 32; iter++) {
        float m = fmaxf(v0, v1);
        #pragma unroll
        for (int off = 16; off; off >>= 1)
            m = fmaxf(m, __shfl_xor_sync(0xffffffffu, m, off));
        if ((tid & 31) == 0) wred[tid >> 5] = m;
        if (tid == 0) claim = 0;
        __syncthreads();
        if (tid == 0) {
            float bm = wred[0];
            #pragma unroll
            for (int w = 1; w < 8; w++) bm = fmaxf(bm, wred[w]);
            sbest = bm;
        }
        __syncthreads();
        const float best = sbest;
        // Remove exactly ONE instance of 'best' (duplicate-safe).
        if (v0 == best) { if (atomicAdd(&claim, 1) == 0) v0 = NEG_INF; }
        if (v1 == best) { if (atomicAdd(&claim, 1) == 0) v1 = NEG_INF; }
        thr = best;
        __syncthreads();
    }

    // degree = count(original row >= thr)
    int cnt = (int)(o0 >= thr) + (int)(o1 >= thr);
    #pragma unroll
    for (int off = 16; off; off >>= 1)
        cnt += __shfl_xor_sync(0xffffffffu, cnt, off);
    __shared__ int wcnt[8];
    if ((tid & 31) == 0) wcnt[tid >> 5] = cnt;
    __syncthreads();
    if (tid == 0) {
        int deg = 0;
        #pragma unroll
        for (int w = 0; w < 8; w++) deg += wcnt[w];
        g_thr[row]  = thr;
        g_rdeg[row] = rsqrtf((float)deg);
    }
}

// ---------------------------------------------------------------------------
// Kernel C: out[b,i,j] = (S[b,i,j] >= thr[b,i]) ? rdeg[b,i]*rdeg[b,j] : 0
// Pure streaming pass, float4-vectorized.
// ---------------------------------------------------------------------------
__global__ __launch_bounds__(256)
void normalize_kernel(float* __restrict__ out)
{
    const size_t idx = (size_t)blockIdx.x * blockDim.x + threadIdx.x; // float4 idx
    const int j4  = (int)(idx % (NN / 4));
    const int row = (int)(idx / (NN / 4));          // 0..BB*NN-1
    const int b   = row / NN;

    const float thr = g_thr[row];
    const float ri  = g_rdeg[row];
    const float4 s  = *(const float4*)(g_S + (size_t)row * NN + j4 * 4);
    const float* rj = g_rdeg + b * NN + j4 * 4;

    float4 o;
    o.x = (s.x >= thr) ? ri * rj[0] : 0.0f;
    o.y = (s.y >= thr) ? ri * rj[1] : 0.0f;
    o.z = (s.z >= thr) ? ri * rj[2] : 0.0f;
    o.w = (s.w >= thr) ? ri * rj[3] : 0.0f;
    ((float4*)out)[idx] = o;
}

// ---------------------------------------------------------------------------
extern "C" void kernel_launch(void* const* d_in, const int* in_sizes, int n_in,
                              void* d_out, int out_size)
{
    const float* x = (const float*)d_in[0];
    float* out = (float*)d_out;

    dim3 gGemm(10, BB);            // 10 symmetric tile-pairs x 64 batches
    gemm_xxt_kernel<<<gGemm, 256>>>(x);

    topk_threshold_kernel<<<BB * NN, 256>>>();

    const int n4 = BB * NN * NN / 4;
    normalize_kernel<<<n4 / 256, 256>>>(out);
}

// round 2
// speedup vs baseline: 1.6528x; 1.6528x over previous
#include <cuda_runtime.h>
#include <cuda_bf16.h>

#define BB 64
#define NN 512
#define CC 1024

typedef unsigned long long ull;

// Scratch (allocation-free rule: __device__ globals)
__device__ float g_S[(size_t)BB * NN * NN];      // 67 MB gram matrices
__device__ float g_thr[BB * NN];                 // per-row 32nd-largest value
__device__ float g_rdeg[BB * NN];                // per-row 1/sqrt(degree)

// ---- packed f32x2 helpers (Blackwell FFMA2 path) -------------------------
__device__ __forceinline__ ull pk2(float x, float y) {
    ull r; asm("mov.b64 %0, {%1, %2};" : "=l"(r) : "f"(x), "f"(y)); return r;
}
__device__ __forceinline__ void fma2(ull &d, ull a, ull b) {
    asm("fma.rn.f32x2 %0, %1, %2, %0;" : "+l"(d) : "l"(a), "l"(b));
}
__device__ __forceinline__ float2 upk2(ull v) {
    float2 r; asm("mov.b64 {%0, %1}, %2;" : "=f"(r.x), "=f"(r.y) : "l"(v)); return r;
}

// ---------------------------------------------------------------------------
// Kernel A: S[b] = X[b] * X[b]^T, symmetric (jt >= it tiles only).
// 128x128 tile / CTA, 256 threads, 8x8 micro-tile per thread, accumulated as
// f32x2 pairs so the fma pipe issues packed FFMA2 (2 FMAs per slot).
// Register-staged double buffering, one __syncthreads per 16-deep k-chunk.
// ---------------------------------------------------------------------------
__global__ __launch_bounds__(256, 2)
void gemm_xxt_kernel(const float* __restrict__ X)
{
    const unsigned char ITm[10] = {0,0,0,0,1,1,1,2,2,3};
    const unsigned char JTm[10] = {0,1,2,3,1,2,3,2,3,3};
    const int it = ITm[blockIdx.x];
    const int jt = JTm[blockIdx.x];
    const int b  = blockIdx.y;

    const float* __restrict__ Xb = X + (size_t)b * NN * CC;

    __shared__ float As[2][16][128];
    __shared__ float Bs[2][16][128];

    const int tid = threadIdx.x;
    const int tx = tid & 15;        // 0..15 -> column groups
    const int ty = tid >> 4;        // 0..15 -> row groups
    const int rbase = it * 128;
    const int cbase = jt * 128;

    // per-thread load slots: l = tid + p*256 -> row = l>>2, k4 = (l&3)*4
    const int lrow0 = tid >> 2,           lk0 = (tid & 3) * 4;
    const int lrow1 = (tid + 256) >> 2,   lk1 = (tid & 3) * 4;   // (l&3) same

    ull acc2[8][4];
    #pragma unroll
    for (int a = 0; a < 8; a++)
        #pragma unroll
        for (int c = 0; c < 4; c++)
            acc2[a][c] = 0ull;

    // prefetch chunk 0 into registers
    float4 ra0, ra1, rb0, rb1;
    ra0 = *(const float4*)(Xb + (size_t)(rbase + lrow0) * CC + lk0);
    ra1 = *(const float4*)(Xb + (size_t)(rbase + lrow1) * CC + lk1);
    rb0 = *(const float4*)(Xb + (size_t)(cbase + lrow0) * CC + lk0);
    rb1 = *(const float4*)(Xb + (size_t)(cbase + lrow1) * CC + lk1);
    // store chunk 0 into buffer 0 (k-major transposed layout)
    {
        As[0][lk0+0][lrow0] = ra0.x; As[0][lk0+1][lrow0] = ra0.y;
        As[0][lk0+2][lrow0] = ra0.z; As[0][lk0+3][lrow0] = ra0.w;
        As[0][lk1+0][lrow1] = ra1.x; As[0][lk1+1][lrow1] = ra1.y;
        As[0][lk1+2][lrow1] = ra1.z; As[0][lk1+3][lrow1] = ra1.w;
        Bs[0][lk0+0][lrow0] = rb0.x; Bs[0][lk0+1][lrow0] = rb0.y;
        Bs[0][lk0+2][lrow0] = rb0.z; Bs[0][lk0+3][lrow0] = rb0.w;
        Bs[0][lk1+0][lrow1] = rb1.x; Bs[0][lk1+1][lrow1] = rb1.y;
        Bs[0][lk1+2][lrow1] = rb1.z; Bs[0][lk1+3][lrow1] = rb1.w;
    }
    __syncthreads();

    int buf = 0;
    for (int k0 = 0; k0 < CC; k0 += 16) {
        const bool has_next = (k0 + 16 < CC);
        if (has_next) {
            const int kn = k0 + 16;
            ra0 = *(const float4*)(Xb + (size_t)(rbase + lrow0) * CC + kn + lk0);
            ra1 = *(const float4*)(Xb + (size_t)(rbase + lrow1) * CC + kn + lk1);
            rb0 = *(const float4*)(Xb + (size_t)(cbase + lrow0) * CC + kn + lk0);
            rb1 = *(const float4*)(Xb + (size_t)(cbase + lrow1) * CC + kn + lk1);
        }

        #pragma unroll
        for (int k = 0; k < 16; k++) {
            float4 a0 = *(const float4*)&As[buf][k][ty * 4];
            float4 a1 = *(const float4*)&As[buf][k][ty * 4 + 64];
            float4 b0 = *(const float4*)&Bs[buf][k][tx * 4];
            float4 b1 = *(const float4*)&Bs[buf][k][tx * 4 + 64];
            ull bp0 = pk2(b0.x, b0.y), bp1 = pk2(b0.z, b0.w);
            ull bp2 = pk2(b1.x, b1.y), bp3 = pk2(b1.z, b1.w);
            float ar[8] = {a0.x, a0.y, a0.z, a0.w, a1.x, a1.y, a1.z, a1.w};
            #pragma unroll
            for (int a = 0; a < 8; a++) {
                ull ad = pk2(ar[a], ar[a]);
                fma2(acc2[a][0], ad, bp0);
                fma2(acc2[a][1], ad, bp1);
                fma2(acc2[a][2], ad, bp2);
                fma2(acc2[a][3], ad, bp3);
            }
        }

        if (has_next) {
            const int nb = buf ^ 1;
            As[nb][lk0+0][lrow0] = ra0.x; As[nb][lk0+1][lrow0] = ra0.y;
            As[nb][lk0+2][lrow0] = ra0.z; As[nb][lk0+3][lrow0] = ra0.w;
            As[nb][lk1+0][lrow1] = ra1.x; As[nb][lk1+1][lrow1] = ra1.y;
            As[nb][lk1+2][lrow1] = ra1.z; As[nb][lk1+3][lrow1] = ra1.w;
            Bs[nb][lk0+0][lrow0] = rb0.x; Bs[nb][lk0+1][lrow0] = rb0.y;
            Bs[nb][lk0+2][lrow0] = rb0.z; Bs[nb][lk0+3][lrow0] = rb0.w;
            Bs[nb][lk1+0][lrow1] = rb1.x; Bs[nb][lk1+1][lrow1] = rb1.y;
            Bs[nb][lk1+2][lrow1] = rb1.z; Bs[nb][lk1+3][lrow1] = rb1.w;
            __syncthreads();
            buf = nb;
        }
    }

    float* __restrict__ Sb = g_S + (size_t)b * NN * NN;
    #pragma unroll
    for (int a = 0; a < 8; a++) {
        const int gr = rbase + ty * 4 + (a & 3) + ((a >> 2) * 64);
        float2 p0 = upk2(acc2[a][0]);
        float2 p1 = upk2(acc2[a][1]);
        float2 p2 = upk2(acc2[a][2]);
        float2 p3 = upk2(acc2[a][3]);
        float4 q0 = make_float4(p0.x, p0.y, p1.x, p1.y);
        float4 q1 = make_float4(p2.x, p2.y, p3.x, p3.y);
        *(float4*)&Sb[(size_t)gr * NN + cbase + tx * 4]      = q0;
        *(float4*)&Sb[(size_t)gr * NN + cbase + 64 + tx * 4] = q1;
        if (jt > it) {
            const int gc = cbase + tx * 4;
            Sb[(size_t)(gc + 0)  * NN + gr] = p0.x;
            Sb[(size_t)(gc + 1)  * NN + gr] = p0.y;
            Sb[(size_t)(gc + 2)  * NN + gr] = p1.x;
            Sb[(size_t)(gc + 3)  * NN + gr] = p1.y;
            Sb[(size_t)(gc + 64) * NN + gr] = p2.x;
            Sb[(size_t)(gc + 65) * NN + gr] = p2.y;
            Sb[(size_t)(gc + 66) * NN + gr] = p3.x;
            Sb[(size_t)(gc + 67) * NN + gr] = p3.y;
        }
    }
}

// ---------------------------------------------------------------------------
// Kernel B: one WARP per row. 512 values live in registers (16/lane).
// 32 rounds of warp-max extraction (shuffles + ballot only, no smem/syncs).
// Exactly one instance removed per round (jax top_k tie semantics).
// degree = 32 + #{survivors >= thr}  (the 32 removed are all >= thr).
// ---------------------------------------------------------------------------
__global__ __launch_bounds__(256)
void topk_threshold_kernel()
{
    const int row  = blockIdx.x * 8 + (threadIdx.x >> 5);   // 8 warps/CTA
    const int lane = threadIdx.x & 31;
    const float* __restrict__ Sr = g_S + (size_t)row * NN;

    const float NEG = __int_as_float(0xff800000);
    float v[16];
    const float4* S4 = (const float4*)Sr;
    #pragma unroll
    for (int j = 0; j < 4; j++) {
        float4 t = S4[lane + 32 * j];
        v[4*j+0] = t.x; v[4*j+1] = t.y; v[4*j+2] = t.z; v[4*j+3] = t.w;
    }

    float lm = v[0];
    #pragma unroll
    for (int j = 1; j < 16; j++) lm = fmaxf(lm, v[j]);

    float thr = NEG;
    #pragma unroll 1
    for (int iter = 0; iter < 32; iter++) {
        float w = lm;
        #pragma unroll
        for (int off = 16; off; off >>= 1)
            w = fmaxf(w, __shfl_xor_sync(0xffffffffu, w, off));
        thr = w;
        unsigned mask = __ballot_sync(0xffffffffu, lm == w);
        int leader = __ffs(mask) - 1;
        if (lane == leader) {
            bool rem = false;
            float nm = NEG;
            #pragma unroll
            for (int j = 0; j < 16; j++) {
                float x = v[j];
                if (!rem && x == w) { x = NEG; v[j] = NEG; rem = true; }
                nm = fmaxf(nm, x);
            }
            lm = nm;
        }
    }

    int cnt = 0;
    #pragma unroll
    for (int j = 0; j < 16; j++) cnt += (v[j] >= thr);
    #pragma unroll
    for (int off = 16; off; off >>= 1)
        cnt += __shfl_xor_sync(0xffffffffu, cnt, off);

    if (lane == 0) {
        g_thr[row]  = thr;
        g_rdeg[row] = rsqrtf((float)(cnt + 32));
    }
}

// ---------------------------------------------------------------------------
// Kernel C: out[b,i,j] = (S[b,i,j] >= thr[b,i]) ? rdeg[b,i]*rdeg[b,j] : 0
// ---------------------------------------------------------------------------
__global__ __launch_bounds__(256)
void normalize_kernel(float* __restrict__ out)
{
    const size_t idx = (size_t)blockIdx.x * blockDim.x + threadIdx.x; // float4 idx
    const int j4  = (int)(idx % (NN / 4));
    const int row = (int)(idx / (NN / 4));
    const int b   = row / NN;

    const float thr = g_thr[row];
    const float ri  = g_rdeg[row];
    const float4 s  = *(const float4*)(g_S + (size_t)row * NN + j4 * 4);
    const float* rj = g_rdeg + b * NN + j4 * 4;

    float4 o;
    o.x = (s.x >= thr) ? ri * rj[0] : 0.0f;
    o.y = (s.y >= thr) ? ri * rj[1] : 0.0f;
    o.z = (s.z >= thr) ? ri * rj[2] : 0.0f;
    o.w = (s.w >= thr) ? ri * rj[3] : 0.0f;
    ((float4*)out)[idx] = o;
}

// ---------------------------------------------------------------------------
extern "C" void kernel_launch(void* const* d_in, const int* in_sizes, int n_in,
                              void* d_out, int out_size)
{
    const float* x = (const float*)d_in[0];
    float* out = (float*)d_out;

    dim3 gGemm(10, BB);            // 10 symmetric tile-pairs x 64 batches
    gemm_xxt_kernel<<<gGemm, 256>>>(x);

    topk_threshold_kernel<<<BB * NN / 8, 256>>>();

    const int n4 = BB * NN * NN / 4;
    normalize_kernel<<<n4 / 256, 256>>>(out);
}

// round 4
// speedup vs baseline: 3.1388x; 1.8991x over previous
#include <cuda_runtime.h>
#include <cuda_fp16.h>
#include <cstdint>

#define BB 64
#define NN 512
#define CC 1024
#define KC 64
#define NCH (CC/KC)          // 16 k-chunks

// Scratch (allocation-free rule: __device__ globals)
__device__ float g_S[(size_t)BB * NN * NN];      // 67 MB gram matrices
__device__ float g_thr[BB * NN];
__device__ float g_rdeg[BB * NN];

// smem: 4 tiles per buffer (A1,A2,B1,B2), 128 rows x 64 halves, padded
// row stride 72 halves (144 B) for conflict-free ldmatrix.
#define ROWB   144
#define TILE_B (128 * ROWB)          // 18432
#define BUF_B  (4 * TILE_B)          // 73728
#define SMEM_TOTAL (2 * BUF_B)       // 147456

__device__ __forceinline__ uint32_t smem_u32(const void* p) {
    uint32_t a;
    asm("{ .reg .u64 t; cvta.to.shared.u64 t, %1; cvt.u32.u64 %0, t; }"
        : "=r"(a) : "l"(p));
    return a;
}
__device__ __forceinline__ void ldsm4(uint32_t& r0, uint32_t& r1,
                                      uint32_t& r2, uint32_t& r3, uint32_t a) {
    asm volatile("ldmatrix.sync.aligned.m8n8.x4.shared.b16 {%0,%1,%2,%3}, [%4];"
                 : "=r"(r0), "=r"(r1), "=r"(r2), "=r"(r3) : "r"(a));
}
__device__ __forceinline__ void mma16816(float* d, const uint32_t* a,
                                         uint32_t b0, uint32_t b1) {
    asm volatile(
        "mma.sync.aligned.m16n8k16.row.col.f32.f16.f16.f32 "
        "{%0,%1,%2,%3}, {%4,%5,%6,%7}, {%8,%9}, {%0,%1,%2,%3};"
        : "+f"(d[0]), "+f"(d[1]), "+f"(d[2]), "+f"(d[3])
        : "r"(a[0]), "r"(a[1]), "r"(a[2]), "r"(a[3]), "r"(b0), "r"(b1));
}

// ---------------------------------------------------------------------------
// Kernel A: HMMA (mma.sync) split-fp16 GEMM.
// S = H1 H1^T + H1 H2^T + H2 H1^T, fp32 accumulation.
// 128x128 tile / CTA over symmetric tile-pairs; fp32->(h1,h2) conversion
// fused into the load path; register-prefetch double buffering.
// ---------------------------------------------------------------------------
__global__ __launch_bounds__(256, 1)
void gemm_mma_kernel(const float* __restrict__ X)
{
    extern __shared__ __align__(16) char smem[];
    const unsigned char ITm[10] = {0,0,0,0,1,1,1,2,2,3};
    const unsigned char JTm[10] = {0,1,2,3,1,2,3,2,3,3};
    const int it = ITm[blockIdx.x];
    const int jt = JTm[blockIdx.x];
    const int b  = blockIdx.y;
    const int rbase = it * 128;
    const int cbase = jt * 128;

    const int tid  = threadIdx.x;
    const int wid  = tid >> 5;
    const int lane = tid & 31;
    const int wm   = wid >> 2;       // 0..1  -> 64-row slab
    const int wn   = wid & 3;        // 0..3  -> 32-col slab
    const uint32_t sb = smem_u32(smem);

    const float* __restrict__ Xb = X + (size_t)b * NN * CC;

    // loader mapping: unit u = i*256 + tid, u in [0,4096)
    //   t = u>>11 (0=A rows, 1=B rows), r = (u>>4)&127, f4 = u&15
    const int lt  = 0;   // placeholder (t varies per i)

    float acc[4][4][4];
    #pragma unroll
    for (int f = 0; f < 4; f++)
        #pragma unroll
        for (int n = 0; n < 4; n++)
            #pragma unroll
            for (int q = 0; q < 4; q++) acc[f][n][q] = 0.0f;

    float4 stage[16];

    auto do_loads = [&](int k0) {
        #pragma unroll
        for (int i = 0; i < 16; i++) {
            int u  = i * 256 + tid;
            int t  = u >> 11;
            int r  = (u >> 4) & 127;
            int f4 = u & 15;
            int grow = (t ? cbase : rbase) + r;
            stage[i] = *(const float4*)(Xb + (size_t)grow * CC + k0 + f4 * 4);
        }
    };
    auto do_stores = [&](int bs) {
        char* base = smem + bs * BUF_B;
        #pragma unroll
        for (int i = 0; i < 16; i++) {
            int u  = i * 256 + tid;
            int t  = u >> 11;
            int r  = (u >> 4) & 127;
            int f4 = u & 15;
            float4 v = stage[i];
            __half2 a1 = __floats2half2_rn(v.x, v.y);
            __half2 b1 = __floats2half2_rn(v.z, v.w);
            float2 fa = __half22float2(a1);
            float2 fb = __half22float2(b1);
            __half2 a2 = __floats2half2_rn(v.x - fa.x, v.y - fa.y);
            __half2 b2 = __floats2half2_rn(v.z - fb.x, v.w - fb.y);
            int off = r * ROWB + f4 * 8;
            *(uint2*)(base + (t*2+0) * TILE_B + off) =
                make_uint2(*(uint32_t*)&a1, *(uint32_t*)&b1);
            *(uint2*)(base + (t*2+1) * TILE_B + off) =
                make_uint2(*(uint32_t*)&a2, *(uint32_t*)&b2);
        }
    };

    do_loads(0);
    do_stores(0);
    __syncthreads();

    // per-warp ldmatrix base offsets
    const int lrow = lane & 15;            // row within 16-row frag
    const int lcol = (lane >> 4) * 16;     // 0 or 16 bytes (k half)

    #pragma unroll 1
    for (int c = 0; c < NCH; c++) {
        const int bs = c & 1;
        if (c + 1 < NCH) do_loads((c + 1) * KC);

        const uint32_t tb = sb + bs * BUF_B;
        const uint32_t pA1 = tb;
        const uint32_t pA2 = tb + TILE_B;
        const uint32_t pB1 = tb + 2 * TILE_B;
        const uint32_t pB2 = tb + 3 * TILE_B;

        #pragma unroll
        for (int ks = 0; ks < 4; ks++) {
            const int kb = ks * 32;  // byte offset along k (16 halves)
            uint32_t a1[4][4], a2[4][4], b1r[2][4], b2r[2][4];
            #pragma unroll
            for (int f = 0; f < 4; f++) {
                int row0 = wm * 64 + f * 16;
                uint32_t ad = (row0 + lrow) * ROWB + lcol + kb;
                ldsm4(a1[f][0], a1[f][1], a1[f][2], a1[f][3], pA1 + ad);
                ldsm4(a2[f][0], a2[f][1], a2[f][2], a2[f][3], pA2 + ad);
            }
            #pragma unroll
            for (int g = 0; g < 2; g++) {
                int n0 = wn * 32 + g * 16;
                uint32_t ad = (n0 + lrow) * ROWB + lcol + kb;
                ldsm4(b1r[g][0], b1r[g][1], b1r[g][2], b1r[g][3], pB1 + ad);
                ldsm4(b2r[g][0], b2r[g][1], b2r[g][2], b2r[g][3], pB2 + ad);
            }
            #pragma unroll
            for (int f = 0; f < 4; f++)
                #pragma unroll
                for (int g = 0; g < 2; g++)
                    #pragma unroll
                    for (int h = 0; h < 2; h++) {
                        float* d = acc[f][g*2+h];
                        mma16816(d, a1[f], b1r[g][0+h], b1r[g][2+h]);
                        mma16816(d, a1[f], b2r[g][0+h], b2r[g][2+h]);
                        mma16816(d, a2[f], b1r[g][0+h], b1r[g][2+h]);
                    }
        }

        if (c + 1 < NCH) {
            do_stores((c + 1) & 1);
            __syncthreads();
        }
    }

    // ---- epilogue: write S tile (+ mirror for off-diagonal pairs) ----
    float* __restrict__ Sb = g_S + (size_t)b * NN * NN;
    const int r0 = lane >> 2;
    const int c0 = (lane & 3) * 2;
    #pragma unroll
    for (int f = 0; f < 4; f++) {
        const int gr = rbase + wm * 64 + f * 16 + r0;
        #pragma unroll
        for (int n = 0; n < 4; n++) {
            const int gc = cbase + wn * 32 + n * 8 + c0;
            float* d = acc[f][n];
            *(float2*)&Sb[(size_t)gr * NN + gc]       = make_float2(d[0], d[1]);
            *(float2*)&Sb[(size_t)(gr + 8) * NN + gc] = make_float2(d[2], d[3]);
            if (jt > it) {
                Sb[(size_t)gc * NN + gr]           = d[0];
                Sb[(size_t)(gc + 1) * NN + gr]     = d[1];
                Sb[(size_t)gc * NN + gr + 8]       = d[2];
                Sb[(size_t)(gc + 1) * NN + gr + 8] = d[3];
            }
        }
    }
}

// ---------------------------------------------------------------------------
// Kernel B: one WARP per row; exact 32nd-largest via bitwise radix select
// on monotone-mapped uint32 keys (REDUX-based counts), then degree.
// ---------------------------------------------------------------------------
__global__ __launch_bounds__(256)
void topk_threshold_kernel()
{
    const int row  = blockIdx.x * 8 + (threadIdx.x >> 5);
    const int lane = threadIdx.x & 31;
    const float* __restrict__ Sr = g_S + (size_t)row * NN;

    uint32_t u[16];
    const float4* S4 = (const float4*)Sr;
    #pragma unroll
    for (int j = 0; j < 4; j++) {
        float4 t = S4[lane + 32 * j];
        float f[4] = {t.x, t.y, t.z, t.w};
        #pragma unroll
        for (int q = 0; q < 4; q++) {
            uint32_t s = __float_as_uint(f[q]);
            u[4*j+q] = (s & 0x80000000u) ? ~s : (s | 0x80000000u);
        }
    }

    uint32_t thr = 0;
    #pragma unroll 1
    for (int bit = 31; bit >= 0; bit--) {
        const uint32_t test = thr | (1u << bit);
        int c = 0;
        #pragma unroll
        for (int j = 0; j < 16; j++) c += (u[j] >= test);
        c = __reduce_add_sync(0xffffffffu, c);
        if (c >= 32) thr = test;
    }

    int cnt = 0;
    #pragma unroll
    for (int j = 0; j < 16; j++) cnt += (u[j] >= thr);
    cnt = __reduce_add_sync(0xffffffffu, cnt);

    if (lane == 0) {
        float tf = (thr & 0x80000000u) ? __uint_as_float(thr & 0x7fffffffu)
                                       : __uint_as_float(~thr);
        g_thr[row]  = tf;
        g_rdeg[row] = rsqrtf((float)cnt);
    }
}

// ---------------------------------------------------------------------------
// Kernel C: out[b,i,j] = (S >= thr_i) ? rdeg_i * rdeg_j : 0
// ---------------------------------------------------------------------------
__global__ __launch_bounds__(256)
void normalize_kernel(float* __restrict__ out)
{
    const size_t idx = (size_t)blockIdx.x * blockDim.x + threadIdx.x;
    const int j4  = (int)(idx % (NN / 4));
    const int row = (int)(idx / (NN / 4));
    const int b   = row / NN;

    const float thr = g_thr[row];
    const float ri  = g_rdeg[row];
    const float4 s  = *(const float4*)(g_S + (size_t)row * NN + j4 * 4);
    const float* rj = g_rdeg + b * NN + j4 * 4;

    float4 o;
    o.x = (s.x >= thr) ? ri * rj[0] : 0.0f;
    o.y = (s.y >= thr) ? ri * rj[1] : 0.0f;
    o.z = (s.z >= thr) ? ri * rj[2] : 0.0f;
    o.w = (s.w >= thr) ? ri * rj[3] : 0.0f;
    ((float4*)out)[idx] = o;
}

// ---------------------------------------------------------------------------
extern "C" void kernel_launch(void* const* d_in, const int* in_sizes, int n_in,
                              void* d_out, int out_size)
{
    const float* x = (const float*)d_in[0];
    float* out = (float*)d_out;

    cudaFuncSetAttribute(gemm_mma_kernel,
                         cudaFuncAttributeMaxDynamicSharedMemorySize, SMEM_TOTAL);

    dim3 gGemm(10, BB);
    gemm_mma_kernel<<<gGemm, 256, SMEM_TOTAL>>>(x);

    topk_threshold_kernel<<<BB * NN / 8, 256>>>();

    const int n4 = BB * NN * NN / 4;
    normalize_kernel<<<n4 / 256, 256>>>(out);
}